// round 15
// baseline (speedup 1.0000x reference)
#include <cuda_runtime.h>
#include <cuda_bf16.h>
#include <math.h>
#include <stdint.h>

#define TT   128      // timesteps
#define BB   128      // batch
#define EMBD 300
#define UU   512
#define GG   2048     // 4*U
#define TBROWS (TT*BB)
#define NBLK 128      // persistent blocks (<=148 SMs -> single wave, spin barrier safe)
#define KMAX2 1536    // max stacked K' for W path (3*512)
#define KU2H 1024     // stored K' for U/h (2 sections: hi|lo)

__device__ __forceinline__ uint32_t smem_u32(const void* p) {
    uint32_t a;
    asm("{ .reg .u64 t; cvta.to.shared.u64 t, %1; cvt.u32.u64 %0, t; }" : "=r"(a) : "l"(p));
    return a;
}

// ---------------- scratch (static device arrays; no allocation) -------------
static __device__ float g_X[TBROWS*EMBD];                 // [t][b][e]
static __device__ float g_Zpre[2][TBROWS*GG];             // per dir: x@W + b for all (t,b)
static __device__ float g_Hseq[2][2][TBROWS*UU];          // [dir][ping][(s*B+r)*U + col]
static __device__ float g_mid[BB*(UU/2)];                 // dense0 output
static __device__ __nv_bfloat16 g_A2[2][(size_t)TBROWS*KMAX2];  // stacked [A_hi|A_hi|A_lo]
static __device__ __nv_bfloat16 g_W2T[2][(size_t)GG*KMAX2];     // [n][k'] stacked [W_hi|W_lo|W_hi]
static __device__ __nv_bfloat16 g_U2T[2][(size_t)GG*KU2H];      // [n][k'] 2 sections [U_hi|U_lo]
static __device__ __nv_bfloat16 g_HT2[2][2][(size_t)KU2H*BB];   // h split K-MAJOR [k'][row], ping-pong

// barrier state. MONOTONE generation: never reset.
static __device__ unsigned g_bar_cnt = 0;
static __device__ unsigned g_bar_gen = 0;

__device__ __forceinline__ void grid_sync(unsigned target) {
    __syncthreads();
    if (threadIdx.x == 0) {
        __threadfence();
        unsigned old = atomicAdd(&g_bar_cnt, 1);
        if (old == NBLK - 1) {
            g_bar_cnt = 0;
            __threadfence();
            atomicAdd(&g_bar_gen, 1);
        } else {
            while (*(volatile unsigned*)&g_bar_gen < target) { }
        }
    }
    __syncthreads();
}

// ---------------- embedding gather ------------------------------------------
__global__ void embed_kernel(const int* __restrict__ ids, const float* __restrict__ emb) {
    int idx = blockIdx.x*256 + threadIdx.x;
    if (idx >= TBROWS*EMBD) return;
    int row = idx / EMBD;
    int e   = idx - row*EMBD;
    int t   = row >> 7;
    int b   = row & 127;
    g_X[idx] = emb[(size_t)ids[b*TT + t]*EMBD + e];
}

// ---------------- bf16 split conversions -------------------------------------
// nsec=3: dst sections [hi | lo | hi] (W path). nsec=2: [hi | lo] (U path).
__global__ void convW_kernel(const float* __restrict__ Wf, const float* __restrict__ Wb,
                             int S, int K2, int K, int toU, int nsec)
{
    int gid = blockIdx.x*256 + threadIdx.x;               // total = 2*S*GG
    int n   = gid & (GG - 1);
    int rest = gid >> 11;
    int kh  = rest % S;
    int dir = rest / S;
    const float* W = dir ? Wb : Wf;
    float v = (kh < K) ? W[(size_t)kh*GG + n] : 0.f;
    __nv_bfloat16 hi = __float2bfloat16(v);
    __nv_bfloat16 lo = __float2bfloat16(v - __bfloat162float(hi));
    __nv_bfloat16* dst = toU ? &g_U2T[dir][(size_t)n*K2 + kh]
                             : &g_W2T[dir][(size_t)n*K2 + kh];
    dst[0] = hi;
    dst[S] = lo;
    if (nsec == 3) dst[2*S] = hi;
}

// A2[dir][m][k'] : sections [A_hi | A_hi | A_lo], zero-padded
__global__ void convA_kernel(int layer, int S, int K2)
{
    int gid = blockIdx.x*256 + threadIdx.x;               // total = 2*TBROWS*S
    int kh  = gid % S;
    int rest = gid / S;
    int m   = rest & (TBROWS - 1);
    int dir = rest >> 14;
    float v;
    if (layer == 0) v = (kh < EMBD) ? g_X[(size_t)m*EMBD + kh] : 0.f;
    else            v = g_Hseq[dir][(layer + 1) & 1][(size_t)m*UU + kh];
    __nv_bfloat16 hi = __float2bfloat16(v);
    __nv_bfloat16 lo = __float2bfloat16(v - __bfloat162float(hi));
    __nv_bfloat16* dst = &g_A2[dir][(size_t)m*K2 + kh];
    dst[0]     = hi;
    dst[S]     = hi;
    dst[2*S]   = lo;
}

// ---------------- tensor-core input projection (R12-proven, unchanged) -------
#define APITCH 40
__global__ void pregemm_mma_kernel(const float* __restrict__ bf_,
                                   const float* __restrict__ bb_, int K2)
{
    __shared__ __align__(16) __nv_bfloat16 As[128*APITCH];
    __shared__ __align__(16) __nv_bfloat16 Bs[64*APITCH];

    int d  = blockIdx.z;
    int n0 = blockIdx.x * 64;
    int m0 = blockIdx.y * 128;
    const __nv_bfloat16* A2 = g_A2[d];
    const __nv_bfloat16* BT = g_W2T[d];
    const float* bias = d ? bb_ : bf_;
    float* Z = g_Zpre[d];

    int tid  = threadIdx.x;
    int wid  = tid >> 5;
    int lane = tid & 31;
    int warp_m = wid >> 1;
    int warp_n = wid & 1;

    uint32_t uA = smem_u32(As);
    uint32_t uB = smem_u32(Bs);

    float acc[2][4][4];
    #pragma unroll
    for (int i = 0; i < 2; ++i)
        #pragma unroll
        for (int j = 0; j < 4; ++j)
            #pragma unroll
            for (int q = 0; q < 4; ++q) acc[i][j][q] = 0.f;

    uint32_t aAddrBase = uA + ((warp_m*32 + (lane & 15))*APITCH + (lane >> 4)*8)*2;
    uint32_t bAddrBase = uB + ((warp_n*32 + (lane & 7) + ((lane >> 4) & 1)*8)*APITCH
                               + ((lane >> 3) & 1)*8)*2;

    int nch = K2 >> 5;
    for (int ch = 0; ch < nch; ++ch) {
        #pragma unroll
        for (int h = 0; h < 2; ++h) {
            int e = tid + h*256;
            int row = e >> 2, c16 = e & 3;
            uint4 v = __ldg((const uint4*)(A2 + (size_t)(m0 + row)*K2 + ch*32) + c16);
            *(uint4*)&As[row*APITCH + c16*8] = v;
        }
        {
            int row = tid >> 2, c16 = tid & 3;
            uint4 v = __ldg((const uint4*)(BT + (size_t)(n0 + row)*K2 + ch*32) + c16);
            *(uint4*)&Bs[row*APITCH + c16*8] = v;
        }
        __syncthreads();

        #pragma unroll
        for (int ks = 0; ks < 2; ++ks) {
            uint32_t a[2][4];
            #pragma unroll
            for (int mt = 0; mt < 2; ++mt) {
                uint32_t addr = aAddrBase + (mt*16*APITCH + ks*16)*2;
                asm volatile("ldmatrix.sync.aligned.m8n8.x4.shared.b16 {%0,%1,%2,%3}, [%4];"
                             : "=r"(a[mt][0]), "=r"(a[mt][1]), "=r"(a[mt][2]), "=r"(a[mt][3])
                             : "r"(addr));
            }
            uint32_t b[4][2];
            #pragma unroll
            for (int nt2 = 0; nt2 < 2; ++nt2) {
                uint32_t addr = bAddrBase + (nt2*16*APITCH + ks*16)*2;
                uint32_t q0, q1, q2, q3;
                asm volatile("ldmatrix.sync.aligned.m8n8.x4.shared.b16 {%0,%1,%2,%3}, [%4];"
                             : "=r"(q0), "=r"(q1), "=r"(q2), "=r"(q3) : "r"(addr));
                b[nt2*2 + 0][0] = q0; b[nt2*2 + 0][1] = q1;
                b[nt2*2 + 1][0] = q2; b[nt2*2 + 1][1] = q3;
            }
            #pragma unroll
            for (int mt = 0; mt < 2; ++mt)
                #pragma unroll
                for (int nt = 0; nt < 4; ++nt) {
                    asm volatile(
                        "mma.sync.aligned.m16n8k16.row.col.f32.bf16.bf16.f32 "
                        "{%0,%1,%2,%3}, {%4,%5,%6,%7}, {%8,%9}, {%0,%1,%2,%3};"
                        : "+f"(acc[mt][nt][0]), "+f"(acc[mt][nt][1]),
                          "+f"(acc[mt][nt][2]), "+f"(acc[mt][nt][3])
                        : "r"(a[mt][0]), "r"(a[mt][1]), "r"(a[mt][2]), "r"(a[mt][3]),
                          "r"(b[nt][0]), "r"(b[nt][1]));
                }
        }
        __syncthreads();
    }

    #pragma unroll
    for (int mt = 0; mt < 2; ++mt) {
        #pragma unroll
        for (int nt = 0; nt < 4; ++nt) {
            int mg = m0 + warp_m*32 + mt*16 + (lane >> 2);
            int ng = n0 + warp_n*32 + nt*8 + 2*(lane & 3);
            float2 bl = *(const float2*)&bias[ng];
            float2 o0 = make_float2(acc[mt][nt][0] + bl.x, acc[mt][nt][1] + bl.y);
            float2 o1 = make_float2(acc[mt][nt][2] + bl.x, acc[mt][nt][3] + bl.y);
            *(float2*)&Z[(size_t)mg*GG + ng]       = o0;
            *(float2*)&Z[(size_t)(mg + 8)*GG + ng] = o1;
        }
    }
}

// ---------------- persistent recurrent layer kernel (HMMA, coalesced) --------
// 128 blocks x 128 threads. Block: dir = bid>>6, 8 h-cols (c0=(bid&63)*8) -> 32
// gate cols. U slice resident in smem [32 n][1024+8 k] (66KB, 2 sections).
// h split stored K-MAJOR [k'][row] (g_HT2): 16 contiguous 16KB chunks/step,
// coalesced ldcg, double-buffered. A frags via ldmatrix.x4.trans. hi chunks run
// 2 B-passes (U_hi, U_lo); lo chunks 1 (U_hi) => full 3-product split.
#define MPITCH 136    // smem h chunk pitch (128 rows + 8)
#define UPITCH2 1032  // smem U pitch (1024 + 8)
__global__ void lstm_layer_kernel(int layer)
{
    extern __shared__ __align__(16) char smem[];
    __nv_bfloat16* U2s = (__nv_bfloat16*)smem;                        // 32*1032
    __nv_bfloat16* As0 = (__nv_bfloat16*)(smem + 32*UPITCH2*2);       // 64*136
    __nv_bfloat16* As1 = (__nv_bfloat16*)(smem + 32*UPITCH2*2 + 64*MPITCH*2);

    int d   = blockIdx.x >> 6;
    int blk = blockIdx.x & 63;
    int c0  = blk << 3;
    const float* Zp = g_Zpre[d];
    float* Hseq = g_Hseq[d][layer & 1];

    int tid  = threadIdx.x;
    int wid  = tid >> 5;
    int lane = tid & 31;
    int row_l = lane >> 2;        // 0..7
    int col_l = 2*(lane & 3);     // 0,2,4,6

    __shared__ unsigned s_base;
    if (tid == 0) s_base = *(volatile unsigned*)&g_bar_gen;

    // resident U2 slice: n_local nl = gate*8 + c -> global col gate*512 + c0 + c
    for (int e = tid; e < 32*128; e += 128) {
        int nl = e >> 7, q = e & 127;
        int ng = (nl >> 3)*512 + c0 + (nl & 7);
        *(uint4*)&U2s[nl*UPITCH2 + q*8] = *(const uint4*)&g_U2T[d][(size_t)ng*KU2H + q*8];
    }
    __syncthreads();
    unsigned base = s_base;

    uint32_t uA0 = smem_u32(As0), uA1 = smem_u32(As1), uU = smem_u32(U2s);
    // A (trans) per-lane term: k_row = (lane&7) + (lane>>4)*8 ; m_off = ((lane>>3)&1)*8
    uint32_t aLane = (((lane & 7) + (lane >> 4)*8)*MPITCH + wid*32 + ((lane >> 3) & 1)*8)*2;
    uint32_t bAddrBase = uU + (((lane & 7) + ((lane >> 4) & 1)*8)*UPITCH2
                               + ((lane >> 3) & 1)*8)*2;

    float c_reg[8];
    #pragma unroll
    for (int i = 0; i < 8; ++i) c_reg[i] = 0.f;

    unsigned bar = 0;
    for (int s = 0; s < TT; ++s) {
        int zr0 = (layer == 0 && d == 1) ? (TT - 1 - s) : s;
        // prefetch Zpre (independent of h -> hides under mainloop)
        float z[2][2][4][2];
        #pragma unroll
        for (int mt = 0; mt < 2; ++mt)
            #pragma unroll
            for (int rr = 0; rr < 2; ++rr) {
                int r = wid*32 + mt*16 + row_l + rr*8;
                const float* zp = Zp + ((size_t)zr0*BB + r)*GG + c0 + col_l;
                #pragma unroll
                for (int g = 0; g < 4; ++g) {
                    float2 v = *(const float2*)&zp[g*512];
                    z[mt][rr][g][0] = v.x; z[mt][rr][g][1] = v.y;
                }
            }

        float acc[2][4][4];
        #pragma unroll
        for (int i = 0; i < 2; ++i)
            #pragma unroll
            for (int j = 0; j < 4; ++j)
                #pragma unroll
                for (int q = 0; q < 4; ++q) acc[i][j][q] = 0.f;

        if (s > 0) {
            const __nv_bfloat16* HT2src = g_HT2[d][(s - 1) & 1];
            uint4 rA[8];
            // stage chunk 0 (contiguous 16KB, coalesced: thread t -> bytes t*128)
            #pragma unroll
            for (int q = 0; q < 8; ++q)
                rA[q] = __ldcg((const uint4*)HT2src + tid*8 + q);
            #pragma unroll
            for (int q = 0; q < 8; ++q)
                *(uint4*)&As0[(tid >> 1)*MPITCH + (tid & 1)*64 + q*8] = rA[q];
            __syncthreads();

            for (int pch = 0; pch < 16; ++pch) {
                if (pch + 1 < 16) {
                    #pragma unroll
                    for (int q = 0; q < 8; ++q)
                        rA[q] = __ldcg((const uint4*)HT2src + (pch + 1)*1024 + tid*8 + q);
                }
                uint32_t uAc = ((pch & 1) ? uA1 : uA0) + aLane;
                int npass = (pch < 8) ? 2 : 1;
                int kU0 = (pch < 8) ? pch*64 : (pch - 8)*64;   // vs U_hi
                int kU1 = 512 + pch*64;                        // vs U_lo (hi chunks only)
                #pragma unroll
                for (int ks = 0; ks < 4; ++ks) {
                    uint32_t a[2][4];
                    #pragma unroll
                    for (int mt = 0; mt < 2; ++mt) {
                        uint32_t addr = uAc + (ks*16*MPITCH + mt*16)*2;
                        asm volatile(
                            "ldmatrix.sync.aligned.m8n8.x4.trans.shared.b16 {%0,%1,%2,%3}, [%4];"
                            : "=r"(a[mt][0]), "=r"(a[mt][1]), "=r"(a[mt][2]), "=r"(a[mt][3])
                            : "r"(addr));
                    }
                    for (int ps = 0; ps < npass; ++ps) {
                        int kU = ps ? kU1 : kU0;
                        uint32_t b[4][2];
                        #pragma unroll
                        for (int nt2 = 0; nt2 < 2; ++nt2) {
                            uint32_t addr = bAddrBase + (kU + ks*16)*2 + nt2*16*UPITCH2*2;
                            uint32_t q0, q1, q2, q3;
                            asm volatile(
                                "ldmatrix.sync.aligned.m8n8.x4.shared.b16 {%0,%1,%2,%3}, [%4];"
                                : "=r"(q0), "=r"(q1), "=r"(q2), "=r"(q3) : "r"(addr));
                            b[nt2*2 + 0][0] = q0; b[nt2*2 + 0][1] = q1;
                            b[nt2*2 + 1][0] = q2; b[nt2*2 + 1][1] = q3;
                        }
                        #pragma unroll
                        for (int mt = 0; mt < 2; ++mt)
                            #pragma unroll
                            for (int nt = 0; nt < 4; ++nt) {
                                asm volatile(
                                    "mma.sync.aligned.m16n8k16.row.col.f32.bf16.bf16.f32 "
                                    "{%0,%1,%2,%3}, {%4,%5,%6,%7}, {%8,%9}, {%0,%1,%2,%3};"
                                    : "+f"(acc[mt][nt][0]), "+f"(acc[mt][nt][1]),
                                      "+f"(acc[mt][nt][2]), "+f"(acc[mt][nt][3])
                                    : "r"(a[mt][0]), "r"(a[mt][1]), "r"(a[mt][2]), "r"(a[mt][3]),
                                      "r"(b[nt][0]), "r"(b[nt][1]));
                            }
                    }
                }
                if (pch + 1 < 16) {
                    __nv_bfloat16* dst = (pch & 1) ? As0 : As1;   // buffer (pch+1)&1
                    #pragma unroll
                    for (int q = 0; q < 8; ++q)
                        *(uint4*)&dst[(tid >> 1)*MPITCH + (tid & 1)*64 + q*8] = rA[q];
                }
                __syncthreads();
            }
        }

        // gates + state update (thread-local: all 4 gates in this thread's frags)
        __nv_bfloat16* HT2dst = g_HT2[d][s & 1];
        int j = c0 + col_l;
        #pragma unroll
        for (int mt = 0; mt < 2; ++mt)
            #pragma unroll
            for (int rr = 0; rr < 2; ++rr) {
                int r = wid*32 + mt*16 + row_l + rr*8;
                float hv[2];
                #pragma unroll
                for (int cc = 0; cc < 2; ++cc) {
                    int q = rr*2 + cc;
                    int i = mt*4 + rr*2 + cc;
                    float zi = acc[mt][0][q] + z[mt][rr][0][cc];
                    float zf = acc[mt][1][q] + z[mt][rr][1][cc];
                    float zg = acc[mt][2][q] + z[mt][rr][2][cc];
                    float zo = acc[mt][3][q] + z[mt][rr][3][cc];
                    float ig = 1.f/(1.f + expf(-zi));
                    float fg = 1.f/(1.f + expf(-zf));
                    float sg = zg/(1.f + fabsf(zg));
                    float og = 1.f/(1.f + expf(-zo));
                    float cn = fg*c_reg[i] + ig*sg;
                    c_reg[i] = cn;
                    float hn = og*(cn/(1.f + fabsf(cn)));
                    hv[cc] = hn;
                    Hseq[((size_t)s*BB + r)*UU + j + cc] = hn;
                }
                __nv_bfloat16 h0 = __float2bfloat16(hv[0]);
                __nv_bfloat16 h1 = __float2bfloat16(hv[1]);
                __nv_bfloat16 l0 = __float2bfloat16(hv[0] - __bfloat162float(h0));
                __nv_bfloat16 l1 = __float2bfloat16(hv[1] - __bfloat162float(h1));
                // k-major: [k][row]; hi at k=j, lo at k=512+j
                HT2dst[(size_t)(j + 0)*BB + r]       = h0;
                HT2dst[(size_t)(j + 1)*BB + r]       = h1;
                HT2dst[(size_t)(512 + j + 0)*BB + r] = l0;
                HT2dst[(size_t)(512 + j + 1)*BB + r] = l1;
            }

        grid_sync(base + (++bar));
    }
}

// ---------------- head: dense0 + BN + PReLU ---------------------------------
__global__ void dense0_kernel(const float* __restrict__ d0W, const float* __restrict__ d0b,
                              const float* __restrict__ gam, const float* __restrict__ bet,
                              const float* __restrict__ mea, const float* __restrict__ var,
                              const float* __restrict__ alp)
{
    int r = blockIdx.x;
    int jj = threadIdx.x;
    __shared__ float addv[UU];
    const float* hf = &g_Hseq[0][0][((size_t)(TT - 1)*BB + r)*UU];   // layer 2 -> ping 0
    const float* hb = &g_Hseq[1][0][((size_t)(TT - 1)*BB + r)*UU];
    for (int k = jj; k < UU; k += 256) addv[k] = 0.5f*(hf[k] + hb[k]);
    __syncthreads();
    float acc = d0b[jj];
    for (int k = 0; k < UU; ++k) acc += addv[k]*d0W[k*(UU/2) + jj];
    float y = (acc - mea[jj])*rsqrtf(var[jj] + 1e-3f)*gam[jj] + bet[jj];
    y = (y > 0.f) ? y : alp[jj]*y;
    g_mid[r*(UU/2) + jj] = y;
}

// ---------------- head: dense1 + softmax ------------------------------------
__global__ void dense1_kernel(const float* __restrict__ d1W, const float* __restrict__ d1b,
                              float* __restrict__ out)
{
    int r = threadIdx.x;
    if (r >= BB) return;
    float lg[7];
    #pragma unroll
    for (int j = 0; j < 7; ++j) lg[j] = d1b[j];
    const float* mid = &g_mid[r*(UU/2)];
    for (int k = 0; k < UU/2; ++k) {
        float v = mid[k];
        #pragma unroll
        for (int j = 0; j < 7; ++j) lg[j] += v*d1W[k*7 + j];
    }
    float m = lg[0];
    #pragma unroll
    for (int j = 1; j < 7; ++j) m = fmaxf(m, lg[j]);
    float ssum = 0.f, e[7];
    #pragma unroll
    for (int j = 0; j < 7; ++j) { e[j] = expf(lg[j] - m); ssum += e[j]; }
    float inv = 1.f/ssum;
    #pragma unroll
    for (int j = 0; j < 7; ++j) out[r*7 + j] = e[j]*inv;
}

// ---------------- launch ----------------------------------------------------
extern "C" void kernel_launch(void* const* d_in, const int* in_sizes, int n_in,
                              void* d_out, int out_size)
{
    (void)in_sizes; (void)n_in; (void)out_size;
    const int*   ids = (const int*)d_in[0];
    const float* emb = (const float*)d_in[1];
    const float* Wm[2][3]; const float* Um[2][3]; const float* bm[2][3];
    for (int d = 0; d < 2; ++d)
        for (int l = 0; l < 3; ++l) {
            int base = 2 + d*9 + l*3;
            Wm[d][l] = (const float*)d_in[base];
            Um[d][l] = (const float*)d_in[base + 1];
            bm[d][l] = (const float*)d_in[base + 2];
        }
    const float* d0W = (const float*)d_in[20];
    const float* d0b = (const float*)d_in[21];
    const float* gam = (const float*)d_in[22];
    const float* bet = (const float*)d_in[23];
    const float* mea = (const float*)d_in[24];
    const float* var = (const float*)d_in[25];
    const float* alp = (const float*)d_in[26];
    const float* d1W = (const float*)d_in[27];
    const float* d1b = (const float*)d_in[28];
    float* out = (float*)d_out;

    const int SMEM_LSTM = 32*UPITCH2*2 + 2*64*MPITCH*2;   // 66048 + 34816 = 100864
    cudaFuncSetAttribute(lstm_layer_kernel,
                         cudaFuncAttributeMaxDynamicSharedMemorySize, SMEM_LSTM);

    embed_kernel<<<(TBROWS*EMBD + 255)/256, 256>>>(ids, emb);

    for (int l = 0; l < 3; ++l) {
        int K  = (l == 0) ? EMBD : UU;     // logical K for W path
        int S  = (l == 0) ? 320  : 512;    // padded section size
        int K2 = 3*S;                      // stacked K' (W path keeps 3 sections)
        convW_kernel<<<(2*S*GG)/256, 256>>>(Wm[0][l], Wm[1][l], S, K2, K, 0, 3);
        convA_kernel<<<(2*TBROWS*S)/256, 256>>>(l, S, K2);
        dim3 gmm(GG/64, TBROWS/128, 2);
        pregemm_mma_kernel<<<gmm, 256>>>(bm[0][l], bm[1][l], K2);
        // U split: 2 sections [hi|lo], K2 = 1024
        convW_kernel<<<(2*512*GG)/256, 256>>>(Um[0][l], Um[1][l], 512, KU2H, 512, 1, 2);
        lstm_layer_kernel<<<NBLK, 128, SMEM_LSTM>>>(l);
    }

    dense0_kernel<<<BB, 256>>>(d0W, d0b, gam, bet, mea, var, alp);
    dense1_kernel<<<1, 128>>>(d1W, d1b, out);
}

// round 16
// speedup vs baseline: 2.0763x; 2.0763x over previous
#include <cuda_runtime.h>
#include <cuda_bf16.h>
#include <math.h>
#include <stdint.h>

#define TT   128      // timesteps
#define BB   128      // batch
#define EMBD 300
#define UU   512
#define GG   2048     // 4*U
#define TBROWS (TT*BB)
#define NBLK 128      // persistent blocks (<=148 SMs -> single wave, spin barrier safe)
#define KMAX2 1536    // max stacked K' for W path (3*512)
#define KU2H 1024     // stored K' for U/h (2 sections: hi|lo)

__device__ __forceinline__ uint32_t smem_u32(const void* p) {
    uint32_t a;
    asm("{ .reg .u64 t; cvta.to.shared.u64 t, %1; cvt.u32.u64 %0, t; }" : "=r"(a) : "l"(p));
    return a;
}

// ---------------- scratch (static device arrays; no allocation) -------------
static __device__ float g_X[TBROWS*EMBD];                 // [t][b][e]
static __device__ float g_Zpre[2][TBROWS*GG];             // per dir: x@W + b for all (t,b)
static __device__ float g_Hseq[2][2][TBROWS*UU];          // [dir][ping][(s*B+r)*U + col]
static __device__ float g_mid[BB*(UU/2)];                 // dense0 output
static __device__ __nv_bfloat16 g_A2[2][(size_t)TBROWS*KMAX2];  // stacked [A_hi|A_hi|A_lo]
static __device__ __nv_bfloat16 g_W2T[2][(size_t)GG*KMAX2];     // [n][k'] stacked [W_hi|W_lo|W_hi]
static __device__ __nv_bfloat16 g_U2T[2][(size_t)GG*KU2H];      // [n][k'] 2 sections [U_hi|U_lo]
static __device__ __nv_bfloat16 g_HT2[2][2][(size_t)KU2H*BB];   // h split K-MAJOR [k'][row], ping-pong

// barrier state. MONOTONE generation: never reset.
static __device__ unsigned g_bar_cnt = 0;
static __device__ unsigned g_bar_gen = 0;

__device__ __forceinline__ void grid_sync(unsigned target) {
    __syncthreads();
    if (threadIdx.x == 0) {
        __threadfence();
        unsigned old = atomicAdd(&g_bar_cnt, 1);
        if (old == NBLK - 1) {
            g_bar_cnt = 0;
            __threadfence();
            atomicAdd(&g_bar_gen, 1);
        } else {
            while (*(volatile unsigned*)&g_bar_gen < target) { }
        }
    }
    __syncthreads();
}

// ---------------- embedding gather ------------------------------------------
__global__ void embed_kernel(const int* __restrict__ ids, const float* __restrict__ emb) {
    int idx = blockIdx.x*256 + threadIdx.x;
    if (idx >= TBROWS*EMBD) return;
    int row = idx / EMBD;
    int e   = idx - row*EMBD;
    int t   = row >> 7;
    int b   = row & 127;
    g_X[idx] = emb[(size_t)ids[b*TT + t]*EMBD + e];
}

// ---------------- bf16 split conversions -------------------------------------
// nsec=3: dst sections [hi | lo | hi] (W path). nsec=2: [hi | lo] (U path).
__global__ void convW_kernel(const float* __restrict__ Wf, const float* __restrict__ Wb,
                             int S, int K2, int K, int toU, int nsec)
{
    int gid = blockIdx.x*256 + threadIdx.x;               // total = 2*S*GG
    int n   = gid & (GG - 1);
    int rest = gid >> 11;
    int kh  = rest % S;
    int dir = rest / S;
    const float* W = dir ? Wb : Wf;
    float v = (kh < K) ? W[(size_t)kh*GG + n] : 0.f;
    __nv_bfloat16 hi = __float2bfloat16(v);
    __nv_bfloat16 lo = __float2bfloat16(v - __bfloat162float(hi));
    __nv_bfloat16* dst = toU ? &g_U2T[dir][(size_t)n*K2 + kh]
                             : &g_W2T[dir][(size_t)n*K2 + kh];
    dst[0] = hi;
    dst[S] = lo;
    if (nsec == 3) dst[2*S] = hi;
}

// A2[dir][m][k'] : sections [A_hi | A_hi | A_lo], zero-padded
__global__ void convA_kernel(int layer, int S, int K2)
{
    int gid = blockIdx.x*256 + threadIdx.x;               // total = 2*TBROWS*S
    int kh  = gid % S;
    int rest = gid / S;
    int m   = rest & (TBROWS - 1);
    int dir = rest >> 14;
    float v;
    if (layer == 0) v = (kh < EMBD) ? g_X[(size_t)m*EMBD + kh] : 0.f;
    else            v = g_Hseq[dir][(layer + 1) & 1][(size_t)m*UU + kh];
    __nv_bfloat16 hi = __float2bfloat16(v);
    __nv_bfloat16 lo = __float2bfloat16(v - __bfloat162float(hi));
    __nv_bfloat16* dst = &g_A2[dir][(size_t)m*K2 + kh];
    dst[0]     = hi;
    dst[S]     = hi;
    dst[2*S]   = lo;
}

// ---------------- tensor-core input projection (R12-proven, unchanged) -------
#define APITCH 40
__global__ void pregemm_mma_kernel(const float* __restrict__ bf_,
                                   const float* __restrict__ bb_, int K2)
{
    __shared__ __align__(16) __nv_bfloat16 As[128*APITCH];
    __shared__ __align__(16) __nv_bfloat16 Bs[64*APITCH];

    int d  = blockIdx.z;
    int n0 = blockIdx.x * 64;
    int m0 = blockIdx.y * 128;
    const __nv_bfloat16* A2 = g_A2[d];
    const __nv_bfloat16* BT = g_W2T[d];
    const float* bias = d ? bb_ : bf_;
    float* Z = g_Zpre[d];

    int tid  = threadIdx.x;
    int wid  = tid >> 5;
    int lane = tid & 31;
    int warp_m = wid >> 1;
    int warp_n = wid & 1;

    uint32_t uA = smem_u32(As);
    uint32_t uB = smem_u32(Bs);

    float acc[2][4][4];
    #pragma unroll
    for (int i = 0; i < 2; ++i)
        #pragma unroll
        for (int j = 0; j < 4; ++j)
            #pragma unroll
            for (int q = 0; q < 4; ++q) acc[i][j][q] = 0.f;

    uint32_t aAddrBase = uA + ((warp_m*32 + (lane & 15))*APITCH + (lane >> 4)*8)*2;
    uint32_t bAddrBase = uB + ((warp_n*32 + (lane & 7) + ((lane >> 4) & 1)*8)*APITCH
                               + ((lane >> 3) & 1)*8)*2;

    int nch = K2 >> 5;
    for (int ch = 0; ch < nch; ++ch) {
        #pragma unroll
        for (int h = 0; h < 2; ++h) {
            int e = tid + h*256;
            int row = e >> 2, c16 = e & 3;
            uint4 v = __ldg((const uint4*)(A2 + (size_t)(m0 + row)*K2 + ch*32) + c16);
            *(uint4*)&As[row*APITCH + c16*8] = v;
        }
        {
            int row = tid >> 2, c16 = tid & 3;
            uint4 v = __ldg((const uint4*)(BT + (size_t)(n0 + row)*K2 + ch*32) + c16);
            *(uint4*)&Bs[row*APITCH + c16*8] = v;
        }
        __syncthreads();

        #pragma unroll
        for (int ks = 0; ks < 2; ++ks) {
            uint32_t a[2][4];
            #pragma unroll
            for (int mt = 0; mt < 2; ++mt) {
                uint32_t addr = aAddrBase + (mt*16*APITCH + ks*16)*2;
                asm volatile("ldmatrix.sync.aligned.m8n8.x4.shared.b16 {%0,%1,%2,%3}, [%4];"
                             : "=r"(a[mt][0]), "=r"(a[mt][1]), "=r"(a[mt][2]), "=r"(a[mt][3])
                             : "r"(addr));
            }
            uint32_t b[4][2];
            #pragma unroll
            for (int nt2 = 0; nt2 < 2; ++nt2) {
                uint32_t addr = bAddrBase + (nt2*16*APITCH + ks*16)*2;
                uint32_t q0, q1, q2, q3;
                asm volatile("ldmatrix.sync.aligned.m8n8.x4.shared.b16 {%0,%1,%2,%3}, [%4];"
                             : "=r"(q0), "=r"(q1), "=r"(q2), "=r"(q3) : "r"(addr));
                b[nt2*2 + 0][0] = q0; b[nt2*2 + 0][1] = q1;
                b[nt2*2 + 1][0] = q2; b[nt2*2 + 1][1] = q3;
            }
            #pragma unroll
            for (int mt = 0; mt < 2; ++mt)
                #pragma unroll
                for (int nt = 0; nt < 4; ++nt) {
                    asm volatile(
                        "mma.sync.aligned.m16n8k16.row.col.f32.bf16.bf16.f32 "
                        "{%0,%1,%2,%3}, {%4,%5,%6,%7}, {%8,%9}, {%0,%1,%2,%3};"
                        : "+f"(acc[mt][nt][0]), "+f"(acc[mt][nt][1]),
                          "+f"(acc[mt][nt][2]), "+f"(acc[mt][nt][3])
                        : "r"(a[mt][0]), "r"(a[mt][1]), "r"(a[mt][2]), "r"(a[mt][3]),
                          "r"(b[nt][0]), "r"(b[nt][1]));
                }
        }
        __syncthreads();
    }

    #pragma unroll
    for (int mt = 0; mt < 2; ++mt) {
        #pragma unroll
        for (int nt = 0; nt < 4; ++nt) {
            int mg = m0 + warp_m*32 + mt*16 + (lane >> 2);
            int ng = n0 + warp_n*32 + nt*8 + 2*(lane & 3);
            float2 bl = *(const float2*)&bias[ng];
            float2 o0 = make_float2(acc[mt][nt][0] + bl.x, acc[mt][nt][1] + bl.y);
            float2 o1 = make_float2(acc[mt][nt][2] + bl.x, acc[mt][nt][3] + bl.y);
            *(float2*)&Z[(size_t)mg*GG + ng]       = o0;
            *(float2*)&Z[(size_t)(mg + 8)*GG + ng] = o1;
        }
    }
}

// ---------------- persistent recurrent layer kernel (HMMA, lane-coalesced) ---
// As R15, ONE FIX: staging loads are lane-major (q*128 + tid) so each LDG.128
// covers a contiguous 2KB warp span (nL=4). uint4 index i = q*128+tid maps to
// k_local = i>>4 = q*8+(tid>>4), row-group = (i&15)*8 = (tid&15)*8.
#define MPITCH 136    // smem h chunk pitch (128 rows + 8)
#define UPITCH2 1032  // smem U pitch (1024 + 8)
__global__ void lstm_layer_kernel(int layer)
{
    extern __shared__ __align__(16) char smem[];
    __nv_bfloat16* U2s = (__nv_bfloat16*)smem;                        // 32*1032
    __nv_bfloat16* As0 = (__nv_bfloat16*)(smem + 32*UPITCH2*2);       // 64*136
    __nv_bfloat16* As1 = (__nv_bfloat16*)(smem + 32*UPITCH2*2 + 64*MPITCH*2);

    int d   = blockIdx.x >> 6;
    int blk = blockIdx.x & 63;
    int c0  = blk << 3;
    const float* Zp = g_Zpre[d];
    float* Hseq = g_Hseq[d][layer & 1];

    int tid  = threadIdx.x;
    int wid  = tid >> 5;
    int lane = tid & 31;
    int row_l = lane >> 2;        // 0..7
    int col_l = 2*(lane & 3);     // 0,2,4,6

    __shared__ unsigned s_base;
    if (tid == 0) s_base = *(volatile unsigned*)&g_bar_gen;

    // resident U2 slice: n_local nl = gate*8 + c -> global col gate*512 + c0 + c
    for (int e = tid; e < 32*128; e += 128) {
        int nl = e >> 7, q = e & 127;
        int ng = (nl >> 3)*512 + c0 + (nl & 7);
        *(uint4*)&U2s[nl*UPITCH2 + q*8] = *(const uint4*)&g_U2T[d][(size_t)ng*KU2H + q*8];
    }
    __syncthreads();
    unsigned base = s_base;

    uint32_t uA0 = smem_u32(As0), uA1 = smem_u32(As1), uU = smem_u32(U2s);
    // A (trans) per-lane term: k_row = (lane&7) + (lane>>4)*8 ; m_off = ((lane>>3)&1)*8
    uint32_t aLane = (((lane & 7) + (lane >> 4)*8)*MPITCH + wid*32 + ((lane >> 3) & 1)*8)*2;
    uint32_t bAddrBase = uU + (((lane & 7) + ((lane >> 4) & 1)*8)*UPITCH2
                               + ((lane >> 3) & 1)*8)*2;
    // lane-major smem store slot for staged uint4 i = q*128+tid
    uint32_t stSlot = (tid >> 4)*MPITCH + (tid & 15)*8;   // element offset; +q*8*MPITCH per q

    float c_reg[8];
    #pragma unroll
    for (int i = 0; i < 8; ++i) c_reg[i] = 0.f;

    unsigned bar = 0;
    for (int s = 0; s < TT; ++s) {
        int zr0 = (layer == 0 && d == 1) ? (TT - 1 - s) : s;
        // prefetch Zpre (independent of h -> hides under mainloop)
        float z[2][2][4][2];
        #pragma unroll
        for (int mt = 0; mt < 2; ++mt)
            #pragma unroll
            for (int rr = 0; rr < 2; ++rr) {
                int r = wid*32 + mt*16 + row_l + rr*8;
                const float* zp = Zp + ((size_t)zr0*BB + r)*GG + c0 + col_l;
                #pragma unroll
                for (int g = 0; g < 4; ++g) {
                    float2 v = *(const float2*)&zp[g*512];
                    z[mt][rr][g][0] = v.x; z[mt][rr][g][1] = v.y;
                }
            }

        float acc[2][4][4];
        #pragma unroll
        for (int i = 0; i < 2; ++i)
            #pragma unroll
            for (int j = 0; j < 4; ++j)
                #pragma unroll
                for (int q = 0; q < 4; ++q) acc[i][j][q] = 0.f;

        if (s > 0) {
            const __nv_bfloat16* HT2src = g_HT2[d][(s - 1) & 1];
            uint4 rA[8];
            // stage chunk 0: lane-major, each LDG.128 covers contiguous 2KB/warp
            #pragma unroll
            for (int q = 0; q < 8; ++q)
                rA[q] = __ldcg((const uint4*)HT2src + q*128 + tid);
            #pragma unroll
            for (int q = 0; q < 8; ++q)
                *(uint4*)&As0[q*8*MPITCH + stSlot] = rA[q];
            __syncthreads();

            for (int pch = 0; pch < 16; ++pch) {
                if (pch + 1 < 16) {
                    #pragma unroll
                    for (int q = 0; q < 8; ++q)
                        rA[q] = __ldcg((const uint4*)HT2src + (pch + 1)*1024 + q*128 + tid);
                }
                uint32_t uAc = ((pch & 1) ? uA1 : uA0) + aLane;
                int npass = (pch < 8) ? 2 : 1;
                int kU0 = (pch < 8) ? pch*64 : (pch - 8)*64;   // vs U_hi
                int kU1 = 512 + pch*64;                        // vs U_lo (hi chunks only)
                #pragma unroll
                for (int ks = 0; ks < 4; ++ks) {
                    uint32_t a[2][4];
                    #pragma unroll
                    for (int mt = 0; mt < 2; ++mt) {
                        uint32_t addr = uAc + (ks*16*MPITCH + mt*16)*2;
                        asm volatile(
                            "ldmatrix.sync.aligned.m8n8.x4.trans.shared.b16 {%0,%1,%2,%3}, [%4];"
                            : "=r"(a[mt][0]), "=r"(a[mt][1]), "=r"(a[mt][2]), "=r"(a[mt][3])
                            : "r"(addr));
                    }
                    for (int ps = 0; ps < npass; ++ps) {
                        int kU = ps ? kU1 : kU0;
                        uint32_t b[4][2];
                        #pragma unroll
                        for (int nt2 = 0; nt2 < 2; ++nt2) {
                            uint32_t addr = bAddrBase + (kU + ks*16)*2 + nt2*16*UPITCH2*2;
                            uint32_t q0, q1, q2, q3;
                            asm volatile(
                                "ldmatrix.sync.aligned.m8n8.x4.shared.b16 {%0,%1,%2,%3}, [%4];"
                                : "=r"(q0), "=r"(q1), "=r"(q2), "=r"(q3) : "r"(addr));
                            b[nt2*2 + 0][0] = q0; b[nt2*2 + 0][1] = q1;
                            b[nt2*2 + 1][0] = q2; b[nt2*2 + 1][1] = q3;
                        }
                        #pragma unroll
                        for (int mt = 0; mt < 2; ++mt)
                            #pragma unroll
                            for (int nt = 0; nt < 4; ++nt) {
                                asm volatile(
                                    "mma.sync.aligned.m16n8k16.row.col.f32.bf16.bf16.f32 "
                                    "{%0,%1,%2,%3}, {%4,%5,%6,%7}, {%8,%9}, {%0,%1,%2,%3};"
                                    : "+f"(acc[mt][nt][0]), "+f"(acc[mt][nt][1]),
                                      "+f"(acc[mt][nt][2]), "+f"(acc[mt][nt][3])
                                    : "r"(a[mt][0]), "r"(a[mt][1]), "r"(a[mt][2]), "r"(a[mt][3]),
                                      "r"(b[nt][0]), "r"(b[nt][1]));
                            }
                    }
                }
                if (pch + 1 < 16) {
                    __nv_bfloat16* dst = (pch & 1) ? As0 : As1;   // buffer (pch+1)&1
                    #pragma unroll
                    for (int q = 0; q < 8; ++q)
                        *(uint4*)&dst[q*8*MPITCH + stSlot] = rA[q];
                }
                __syncthreads();
            }
        }

        // gates + state update (thread-local: all 4 gates in this thread's frags)
        __nv_bfloat16* HT2dst = g_HT2[d][s & 1];
        int j = c0 + col_l;
        #pragma unroll
        for (int mt = 0; mt < 2; ++mt)
            #pragma unroll
            for (int rr = 0; rr < 2; ++rr) {
                int r = wid*32 + mt*16 + row_l + rr*8;
                float hv[2];
                #pragma unroll
                for (int cc = 0; cc < 2; ++cc) {
                    int q = rr*2 + cc;
                    int i = mt*4 + rr*2 + cc;
                    float zi = acc[mt][0][q] + z[mt][rr][0][cc];
                    float zf = acc[mt][1][q] + z[mt][rr][1][cc];
                    float zg = acc[mt][2][q] + z[mt][rr][2][cc];
                    float zo = acc[mt][3][q] + z[mt][rr][3][cc];
                    float ig = 1.f/(1.f + expf(-zi));
                    float fg = 1.f/(1.f + expf(-zf));
                    float sg = zg/(1.f + fabsf(zg));
                    float og = 1.f/(1.f + expf(-zo));
                    float cn = fg*c_reg[i] + ig*sg;
                    c_reg[i] = cn;
                    float hn = og*(cn/(1.f + fabsf(cn)));
                    hv[cc] = hn;
                    Hseq[((size_t)s*BB + r)*UU + j + cc] = hn;
                }
                __nv_bfloat16 h0 = __float2bfloat16(hv[0]);
                __nv_bfloat16 h1 = __float2bfloat16(hv[1]);
                __nv_bfloat16 l0 = __float2bfloat16(hv[0] - __bfloat162float(h0));
                __nv_bfloat16 l1 = __float2bfloat16(hv[1] - __bfloat162float(h1));
                // k-major: [k][row]; hi at k=j, lo at k=512+j
                HT2dst[(size_t)(j + 0)*BB + r]       = h0;
                HT2dst[(size_t)(j + 1)*BB + r]       = h1;
                HT2dst[(size_t)(512 + j + 0)*BB + r] = l0;
                HT2dst[(size_t)(512 + j + 1)*BB + r] = l1;
            }

        grid_sync(base + (++bar));
    }
}

// ---------------- head: dense0 + BN + PReLU ---------------------------------
__global__ void dense0_kernel(const float* __restrict__ d0W, const float* __restrict__ d0b,
                              const float* __restrict__ gam, const float* __restrict__ bet,
                              const float* __restrict__ mea, const float* __restrict__ var,
                              const float* __restrict__ alp)
{
    int r = blockIdx.x;
    int jj = threadIdx.x;
    __shared__ float addv[UU];
    const float* hf = &g_Hseq[0][0][((size_t)(TT - 1)*BB + r)*UU];   // layer 2 -> ping 0
    const float* hb = &g_Hseq[1][0][((size_t)(TT - 1)*BB + r)*UU];
    for (int k = jj; k < UU; k += 256) addv[k] = 0.5f*(hf[k] + hb[k]);
    __syncthreads();
    float acc = d0b[jj];
    for (int k = 0; k < UU; ++k) acc += addv[k]*d0W[k*(UU/2) + jj];
    float y = (acc - mea[jj])*rsqrtf(var[jj] + 1e-3f)*gam[jj] + bet[jj];
    y = (y > 0.f) ? y : alp[jj]*y;
    g_mid[r*(UU/2) + jj] = y;
}

// ---------------- head: dense1 + softmax ------------------------------------
__global__ void dense1_kernel(const float* __restrict__ d1W, const float* __restrict__ d1b,
                              float* __restrict__ out)
{
    int r = threadIdx.x;
    if (r >= BB) return;
    float lg[7];
    #pragma unroll
    for (int j = 0; j < 7; ++j) lg[j] = d1b[j];
    const float* mid = &g_mid[r*(UU/2)];
    for (int k = 0; k < UU/2; ++k) {
        float v = mid[k];
        #pragma unroll
        for (int j = 0; j < 7; ++j) lg[j] += v*d1W[k*7 + j];
    }
    float m = lg[0];
    #pragma unroll
    for (int j = 1; j < 7; ++j) m = fmaxf(m, lg[j]);
    float ssum = 0.f, e[7];
    #pragma unroll
    for (int j = 0; j < 7; ++j) { e[j] = expf(lg[j] - m); ssum += e[j]; }
    float inv = 1.f/ssum;
    #pragma unroll
    for (int j = 0; j < 7; ++j) out[r*7 + j] = e[j]*inv;
}

// ---------------- launch ----------------------------------------------------
extern "C" void kernel_launch(void* const* d_in, const int* in_sizes, int n_in,
                              void* d_out, int out_size)
{
    (void)in_sizes; (void)n_in; (void)out_size;
    const int*   ids = (const int*)d_in[0];
    const float* emb = (const float*)d_in[1];
    const float* Wm[2][3]; const float* Um[2][3]; const float* bm[2][3];
    for (int d = 0; d < 2; ++d)
        for (int l = 0; l < 3; ++l) {
            int base = 2 + d*9 + l*3;
            Wm[d][l] = (const float*)d_in[base];
            Um[d][l] = (const float*)d_in[base + 1];
            bm[d][l] = (const float*)d_in[base + 2];
        }
    const float* d0W = (const float*)d_in[20];
    const float* d0b = (const float*)d_in[21];
    const float* gam = (const float*)d_in[22];
    const float* bet = (const float*)d_in[23];
    const float* mea = (const float*)d_in[24];
    const float* var = (const float*)d_in[25];
    const float* alp = (const float*)d_in[26];
    const float* d1W = (const float*)d_in[27];
    const float* d1b = (const float*)d_in[28];
    float* out = (float*)d_out;

    const int SMEM_LSTM = 32*UPITCH2*2 + 2*64*MPITCH*2;   // 66048 + 34816 = 100864
    cudaFuncSetAttribute(lstm_layer_kernel,
                         cudaFuncAttributeMaxDynamicSharedMemorySize, SMEM_LSTM);

    embed_kernel<<<(TBROWS*EMBD + 255)/256, 256>>>(ids, emb);

    for (int l = 0; l < 3; ++l) {
        int K  = (l == 0) ? EMBD : UU;     // logical K for W path
        int S  = (l == 0) ? 320  : 512;    // padded section size
        int K2 = 3*S;                      // stacked K' (W path keeps 3 sections)
        convW_kernel<<<(2*S*GG)/256, 256>>>(Wm[0][l], Wm[1][l], S, K2, K, 0, 3);
        convA_kernel<<<(2*TBROWS*S)/256, 256>>>(l, S, K2);
        dim3 gmm(GG/64, TBROWS/128, 2);
        pregemm_mma_kernel<<<gmm, 256>>>(bm[0][l], bm[1][l], K2);
        // U split: 2 sections [hi|lo], K2 = 1024
        convW_kernel<<<(2*512*GG)/256, 256>>>(Um[0][l], Um[1][l], 512, KU2H, 512, 1, 2);
        lstm_layer_kernel<<<NBLK, 128, SMEM_LSTM>>>(l);
    }

    dense0_kernel<<<BB, 256>>>(d0W, d0b, gam, bet, mea, var, alp);
    dense1_kernel<<<1, 128>>>(d1W, d1b, out);
}